// round 4
// baseline (speedup 1.0000x reference)
#include <cuda_runtime.h>

// 8192x8192 fp32 input; 10 3x3 SAME convs; 4 2x2 maxpools.
// Stages: [conv,conv,pool] x2 then [conv,conv,conv,pool] x2.

__device__ float g_buf0[4096u * 4096u];
__device__ float g_buf1[2048u * 2048u];
__device__ float g_buf2[1024u * 1024u];

// ---- packed fp32x2 math (Blackwell sm_100+) ----
__device__ __forceinline__ float2 ffma2(float2 a, float2 b, float2 c) {
    float2 d;
    asm("fma.rn.f32x2 %0, %1, %2, %3;"
        : "=l"(*(unsigned long long*)&d)
        : "l"(*(unsigned long long*)&a),
          "l"(*(unsigned long long*)&b),
          "l"(*(unsigned long long*)&c));
    return d;
}
__device__ __forceinline__ float2 fmul2(float2 a, float2 b) {
    float2 d;
    asm("mul.rn.f32x2 %0, %1, %2;"
        : "=l"(*(unsigned long long*)&d)
        : "l"(*(unsigned long long*)&a),
          "l"(*(unsigned long long*)&b));
    return d;
}

// Load 8 floats (2 aligned float4) and build the 5 sliding pairs starting at C.
template <int C>
__device__ __forceinline__ void load_row_pairs(float2 p[5], const float* src) {
    float4 A = *(const float4*)(src);
    float4 B = *(const float4*)(src + 4);
    float w[8] = {A.x, A.y, A.z, A.w, B.x, B.y, B.z, B.w};
#pragma unroll
    for (int i = 0; i < 5; ++i) p[i] = make_float2(w[C + i], w[C + i + 1]);
}

// One conv layer over the fixed RCP x RCP region at offset (C+1).
// Each active thread: 4x4 outputs via two f32x2 tap chains, rolling 3-row
// pair window. Image-edge SAME zeroing only on edge blocks.
template <int C, int B>
__device__ __forceinline__ void run_layer(
    const float* __restrict__ src, float* __restrict__ dst,
    const float* __restrict__ wts, int s, int g, bool active, bool edge,
    int gx0, int gy0, unsigned uw) {
    if (active) {
        float2 k2[9];
#pragma unroll
        for (int m = 0; m < 9; ++m) {
            float kv = wts[C * 9 + m];
            k2[m] = make_float2(kv, kv);
        }
        const int colbase = (C + 1) + 4 * s;
        const int rowtop  = C + 4 * g;
        const float* sp = src + rowtop * B + 4 * s;

        float2 P[3][5];
        load_row_pairs<C>(P[0], sp);
        load_row_pairs<C>(P[1], sp + B);

#pragma unroll
        for (int j = 0; j < 4; ++j) {
            load_row_pairs<C>(P[(j + 2) % 3], sp + (2 + j) * B);
            const float2* r0 = P[j % 3];
            const float2* r1 = P[(j + 1) % 3];
            const float2* r2 = P[(j + 2) % 3];

            // outputs (colbase, colbase+1): tap m uses pair[m]
            float2 a0 = fmul2(r0[0], k2[0]);
            a0 = ffma2(r0[1], k2[1], a0);
            a0 = ffma2(r0[2], k2[2], a0);
            a0 = ffma2(r1[0], k2[3], a0);
            a0 = ffma2(r1[1], k2[4], a0);
            a0 = ffma2(r1[2], k2[5], a0);
            a0 = ffma2(r2[0], k2[6], a0);
            a0 = ffma2(r2[1], k2[7], a0);
            a0 = ffma2(r2[2], k2[8], a0);
            // outputs (colbase+2, colbase+3): tap m uses pair[m+2]
            float2 a1 = fmul2(r0[2], k2[0]);
            a1 = ffma2(r0[3], k2[1], a1);
            a1 = ffma2(r0[4], k2[2], a1);
            a1 = ffma2(r1[2], k2[3], a1);
            a1 = ffma2(r1[3], k2[4], a1);
            a1 = ffma2(r1[4], k2[5], a1);
            a1 = ffma2(r2[2], k2[6], a1);
            a1 = ffma2(r2[3], k2[7], a1);
            a1 = ffma2(r2[4], k2[8], a1);

            const int oy = (C + 1) + 4 * g + j;
            float* dp = dst + oy * B + colbase;
            if (!edge) {
                dp[0] = a0.x; dp[1] = a0.y; dp[2] = a1.x; dp[3] = a1.y;
            } else {
                // SAME zero-padding at the image boundary, re-applied per layer.
                const bool rok = (unsigned)(gy0 + oy) < uw;
                float v[4] = {a0.x, a0.y, a1.x, a1.y};
#pragma unroll
                for (int q = 0; q < 4; ++q)
                    dp[q] = (rok && ((unsigned)(gx0 + colbase + q) < uw)) ? v[q] : 0.0f;
            }
        }
    }
    __syncthreads();
}

// Fused stage: K 3x3 convs + 2x2 maxpool. Block -> TO x TO pooled tile.
template <int K, int TO, int NT, int MINCTA>
__global__ __launch_bounds__(NT, MINCTA)
void stage_kernel(const float* __restrict__ in, int inW,
                  float* __restrict__ out, int outW,
                  const float* __restrict__ w0,
                  const float* __restrict__ w1,
                  const float* __restrict__ w2) {
    constexpr int EXT    = 2 * TO + 2 * K;                 // loaded extent
    constexpr int RCP    = (2 * TO + 2 * K - 2 + 3) & ~3;  // per-layer compute region
    constexpr int STRIPS = RCP / 4;
    constexpr int NACT   = STRIPS * STRIPS;
    constexpr int B      = RCP + 4;                        // buffer dim (rows=cols)

    __shared__ float bufA[B * B];
    __shared__ float bufB[B * B];
    __shared__ float wts[27];

    const int tid = threadIdx.x;
    if (tid < K * 9) {
        const float* wp = (tid < 9) ? w0 : ((tid < 18) ? w1 : w2);
        wts[tid] = wp[tid % 9];
    }

    const int gx0 = blockIdx.x * 2 * TO - K;
    const int gy0 = blockIdx.y * 2 * TO - K;
    const unsigned uw = (unsigned)inW;  // square image
    const bool edge = (gx0 < 0) || (gy0 < 0) ||
                      (gx0 + EXT > inW) || (gy0 + EXT > inW);

    // Load input region (coalesced along rows); zero pad; zero bufB.
    {
        constexpr int LROWS = NT / B;  // concurrent rows
        const int tc = tid % B;
        const int tr = tid / B;
        if (tr < LROWS) {
            const bool colin = (tc < EXT) &&
                               (!edge || ((unsigned)(gx0 + tc) < uw));
            for (int r = tr; r < B; r += LROWS) {
                float v = 0.0f;
                if (colin && r < EXT && (!edge || ((unsigned)(gy0 + r) < uw)))
                    v = in[(long)(gy0 + r) * inW + (gx0 + tc)];
                bufA[r * B + tc] = v;
                bufB[r * B + tc] = 0.0f;
            }
        }
    }
    __syncthreads();

    const bool active = tid < NACT;
    const int s = tid % STRIPS;
    const int g = tid / STRIPS;

    float* src = bufA;
    float* dst = bufB;

    run_layer<0, B>(src, dst, wts, s, g, active, edge, gx0, gy0, uw);
    { float* t = src; src = dst; dst = t; }
    run_layer<1, B>(src, dst, wts, s, g, active, edge, gx0, gy0, uw);
    { float* t = src; src = dst; dst = t; }
    if (K == 3) {
        run_layer<2, B>(src, dst, wts, s, g, active, edge, gx0, gy0, uw);
        float* t = src; src = dst; dst = t;
    }

    // 2x2 max pool over [K, K+2TO)^2 -> TO x TO pooled tile.
    for (int i = tid; i < TO * TO; i += NT) {
        int py = i / TO, px = i % TO;
        const float* p = src + (K + 2 * py) * B + (K + 2 * px);
        float m = fmaxf(fmaxf(p[0], p[1]), fmaxf(p[B], p[B + 1]));
        out[(long)(blockIdx.y * TO + py) * outW + blockIdx.x * TO + px] = m;
    }
}

extern "C" void kernel_launch(void* const* d_in, const int* in_sizes, int n_in,
                              void* d_out, int out_size) {
    const float* x = (const float*)d_in[0];
    const float* w[10];
    for (int i = 0; i < 10; ++i) w[i] = (const float*)d_in[1 + i];

    float *b0, *b1, *b2;
    cudaGetSymbolAddress((void**)&b0, g_buf0);
    cudaGetSymbolAddress((void**)&b1, g_buf1);
    cudaGetSymbolAddress((void**)&b2, g_buf2);

    float* outp = (float*)d_out;

    // Stage A: 8192 -> cc pool -> 4096   (TO=32 tiles, 320 thr)
    stage_kernel<2, 32, 320, 3><<<dim3(128, 128), 320>>>(x,  8192, b0, 4096, w[0], w[1], nullptr);
    // Stage B: 4096 -> cc pool -> 2048
    stage_kernel<2, 32, 320, 3><<<dim3(64, 64),   320>>>(b0, 4096, b1, 2048, w[2], w[3], nullptr);
    // Stage C: 2048 -> ccc pool -> 1024  (TO=16 tiles for occupancy)
    stage_kernel<3, 16, 96, 8><<<dim3(64, 64),    96>>>(b1, 2048, b2, 1024, w[4], w[5], w[6]);
    // Stage D: 1024 -> ccc pool -> 512
    stage_kernel<3, 16, 96, 8><<<dim3(32, 32),    96>>>(b2, 1024, outp, 512, w[7], w[8], w[9]);
}

// round 5
// speedup vs baseline: 2.7596x; 2.7596x over previous
#include <cuda_runtime.h>

// 8192x8192 fp32 input; 10 3x3 SAME convs; 4 2x2 maxpools.
// Stages: [conv,conv,pool] x2 then [conv,conv,conv,pool] x2.

__device__ float g_buf0[4096u * 4096u];
__device__ float g_buf1[2048u * 2048u];
__device__ float g_buf2[1024u * 1024u];

#define NT 320                 // threads per block (10 warps)
#define BD 72                  // smem buffer dim (stride), 16B-aligned rows
#define STRIPS 17              // 17 x 17 threads x (4x4 px) cover 68x68
#define NACT (STRIPS * STRIPS) // 289 active conv threads

// Load 8 consecutive floats (two aligned float4) from smem.
__device__ __forceinline__ void ld8(float* d, const float* p) {
    float4 a = *(const float4*)(p);
    float4 b = *(const float4*)(p + 4);
    d[0] = a.x; d[1] = a.y; d[2] = a.z; d[3] = a.w;
    d[4] = b.x; d[5] = b.y; d[6] = b.z; d[7] = b.w;
}

__device__ __forceinline__ void conv_row(float v[4], const float* r0,
                                         const float* r1, const float* r2,
                                         const float k[9]) {
#pragma unroll
    for (int q = 0; q < 4; ++q) {
        v[q] = r0[q] * k[0] + r0[q + 1] * k[1] + r0[q + 2] * k[2]
             + r1[q] * k[3] + r1[q + 1] * k[4] + r1[q + 2] * k[5]
             + r2[q] * k[6] + r2[q + 1] * k[7] + r2[q + 2] * k[8];
    }
}

// One conv layer with shifted-origin output: dst[r][x] = conv(src)[r+1][x+1].
// Every layer therefore reads ld8 at col 4s (window offset 0) and stores an
// aligned float4 at col 4s. EDGE: re-apply SAME zero padding at the image
// boundary; dst(r,x) has absolute coords (ey0+r, ex0+x).
template <bool EDGE>
__device__ __forceinline__ void layer_mid(const float* __restrict__ src,
                                          float* __restrict__ dst,
                                          const float k[9], int s, int g,
                                          int ey0, int ex0, unsigned uw) {
    const float* sp = src + (4 * g) * BD + 4 * s;
    float r[3][8];
    ld8(r[0], sp);
    ld8(r[1], sp + BD);
#pragma unroll
    for (int j = 0; j < 4; ++j) {
        ld8(r[(j + 2) % 3], sp + (2 + j) * BD);
        float v[4];
        conv_row(v, r[j % 3], r[(j + 1) % 3], r[(j + 2) % 3], k);
        if (EDGE) {
            const bool rok = (unsigned)(ey0 + 4 * g + j) < uw;
#pragma unroll
            for (int q = 0; q < 4; ++q)
                if (!(rok && ((unsigned)(ex0 + 4 * s + q) < uw))) v[q] = 0.0f;
        }
        *(float4*)(dst + (4 * g + j) * BD + 4 * s) =
            make_float4(v[0], v[1], v[2], v[3]);
    }
}

// Last conv layer fused with 2x2 maxpool (interior blocks; s,g < 16).
// Thread's 4x4 output block is pool-aligned -> 2x2 pooled px -> direct STG.
__device__ __forceinline__ void layer_last_pool(const float* __restrict__ src,
                                                float* __restrict__ out,
                                                int outW, const float k[9],
                                                int s, int g, int oy, int ox) {
    const float* sp = src + (4 * g) * BD + 4 * s;
    float r[3][8];
    ld8(r[0], sp);
    ld8(r[1], sp + BD);
    float p[2][2];
#pragma unroll
    for (int j = 0; j < 4; ++j) {
        ld8(r[(j + 2) % 3], sp + (2 + j) * BD);
        float v[4];
        conv_row(v, r[j % 3], r[(j + 1) % 3], r[(j + 2) % 3], k);
        const int pr = j >> 1;
        float m0 = fmaxf(v[0], v[1]);
        float m1 = fmaxf(v[2], v[3]);
        if ((j & 1) == 0) { p[pr][0] = m0; p[pr][1] = m1; }
        else             { p[pr][0] = fmaxf(p[pr][0], m0);
                           p[pr][1] = fmaxf(p[pr][1], m1); }
    }
    float* op = out + (long)(oy + 2 * g) * outW + (ox + 2 * s);
    *(float2*)op = make_float2(p[0][0], p[0][1]);
    *(float2*)(op + outW) = make_float2(p[1][0], p[1][1]);
}

// Fused stage: K 3x3 convs (SAME at image boundary) + 2x2 maxpool.
// Block -> 32x32 pooled tile (64x64 pre-pool). EXT = 64 + 2K loaded extent.
template <int K>
__global__ __launch_bounds__(NT, 4)
void stage_kernel(const float* __restrict__ in, int inW,
                  float* __restrict__ out, int outW,
                  const float* __restrict__ w0,
                  const float* __restrict__ w1,
                  const float* __restrict__ w2) {
    constexpr int EXT = 64 + 2 * K;
    __shared__ float bufA[BD * BD];
    __shared__ float bufB[BD * BD];
    __shared__ float wts[27];

    const int tid = threadIdx.x;
    if (tid < K * 9) {
        const float* wp = (tid < 9) ? w0 : ((tid < 18) ? w1 : w2);
        wts[tid] = wp[tid % 9];
    }

    const int gx0 = blockIdx.x * 64 - K;
    const int gy0 = blockIdx.y * 64 - K;
    const unsigned uw = (unsigned)inW;  // square image
    const bool edge = (gx0 < 0) || (gy0 < 0) ||
                      (gx0 + EXT > inW) || (gy0 + EXT > inW);

    // Zero bufB (rim must be finite; interior of it gets overwritten).
    for (int i = tid; i < BD * BD / 4; i += NT)
        ((float4*)bufB)[i] = make_float4(0.f, 0.f, 0.f, 0.f);

    // Load input region into bufA (zero outside EXT / outside image).
    if (!edge && K == 2) {
        // Interior, K=2: gx0 is even -> aligned float2 global loads.
        if (tid < 288) {
            const int tc = tid % 36;            // float2 column
            const int tr = tid / 36;            // 8 concurrent rows
            const float* gp = in + (long)(gy0 + tr) * inW + gx0 + 2 * tc;
            const bool colin = (tc <= 33);      // cols < 68
#pragma unroll
            for (int r = tr; r < BD; r += 8, gp += 8L * inW) {
                float2 v = make_float2(0.f, 0.f);
                if (colin && r < EXT) v = *(const float2*)gp;
                *(float2*)&bufA[r * BD + 2 * tc] = v;
            }
        }
    } else {
        for (int i = tid; i < BD * BD; i += NT) {
            int r = i / BD, c = i - r * BD;
            float v = 0.0f;
            if (r < EXT && c < EXT) {
                int gy = gy0 + r, gx = gx0 + c;
                if (!edge || ((unsigned)gy < uw && (unsigned)gx < uw))
                    v = in[(long)gy * inW + gx];
            }
            bufA[i] = v;
        }
    }
    __syncthreads();

    const bool active = tid < NACT;
    const int s = tid % STRIPS;
    const int g = tid / STRIPS;
    const int ox = blockIdx.x * 32, oy = blockIdx.y * 32;

    float k[9];
    float* src = bufA;
    float* dst = bufB;

    // ---- layers 0 .. K-2 (to smem) ----
#pragma unroll
    for (int c = 0; c < K - 1; ++c) {
        if (active) {
#pragma unroll
            for (int m = 0; m < 9; ++m) k[m] = wts[c * 9 + m];
            if (edge) layer_mid<true >(src, dst, k, s, g,
                                       gy0 + c + 1, gx0 + c + 1, uw);
            else      layer_mid<false>(src, dst, k, s, g, 0, 0, uw);
        }
        __syncthreads();
        float* t = src; src = dst; dst = t;
    }

    // ---- last layer ----
    if (!edge) {
        if (s < 16 && g < 16 && active) {
#pragma unroll
            for (int m = 0; m < 9; ++m) k[m] = wts[(K - 1) * 9 + m];
            layer_last_pool(src, out, outW, k, s, g, oy, ox);
        }
        // no further smem use; no sync needed before exit
    } else {
        if (active) {
#pragma unroll
            for (int m = 0; m < 9; ++m) k[m] = wts[(K - 1) * 9 + m];
            layer_mid<true>(src, dst, k, s, g, gy0 + K, gx0 + K, uw);
        }
        __syncthreads();
        // Pool over dst [0,64)^2 (shifted coords: buf 0 == abs blockIdx*64).
        for (int i = tid; i < 1024; i += NT) {
            int py = i >> 5, px = i & 31;
            const float* p = dst + (2 * py) * BD + 2 * px;
            float m = fmaxf(fmaxf(p[0], p[1]), fmaxf(p[BD], p[BD + 1]));
            out[(long)(oy + py) * outW + ox + px] = m;
        }
    }
}

extern "C" void kernel_launch(void* const* d_in, const int* in_sizes, int n_in,
                              void* d_out, int out_size) {
    const float* x = (const float*)d_in[0];
    const float* w[10];
    for (int i = 0; i < 10; ++i) w[i] = (const float*)d_in[1 + i];

    float *b0, *b1, *b2;
    cudaGetSymbolAddress((void**)&b0, g_buf0);
    cudaGetSymbolAddress((void**)&b1, g_buf1);
    cudaGetSymbolAddress((void**)&b2, g_buf2);

    float* outp = (float*)d_out;

    stage_kernel<2><<<dim3(128, 128), NT>>>(x,  8192, b0,  4096, w[0], w[1], nullptr);
    stage_kernel<2><<<dim3(64, 64),   NT>>>(b0, 4096, b1,  2048, w[2], w[3], nullptr);
    stage_kernel<3><<<dim3(32, 32),   NT>>>(b1, 2048, b2,  1024, w[4], w[5], w[6]);
    stage_kernel<3><<<dim3(16, 16),   NT>>>(b2, 1024, outp, 512, w[7], w[8], w[9]);
}